// round 4
// baseline (speedup 1.0000x reference)
#include <cuda_runtime.h>

// LJ_8718783611256: log_prob = -(LJ pair potential + harmonic confinement)
// x: (4, 2048, 3) float32, out: (4,) float32
//
// R4: triangle tiles 128i x 128j, TPB=256 with the j-tile split in half
// across the two warp-groups (more warps/SM -> hide LDS/MUFU latency).
// Interleaved padded smem layout (LDS.128 + LDS.64 per packed iter).
// Packed f32x2 math, fused harmonic, memset-init + atomicAdd.

#define NB      4
#define NPTS    2048
#define IT      128          // i-rows per tile
#define JT      128          // j-cols per tile
#define TPB     256          // 2 threads per i-row (one per j-half)
#define NCHUNK  (NPTS / JT)  // 16
#define NTRI    (NCHUNK * (NCHUNK + 1) / 2)  // 136

typedef unsigned long long ull;

#define FMA2(d, a, b, c) \
    asm("fma.rn.f32x2 %0, %1, %2, %3;" : "=l"(d) : "l"(a), "l"(b), "l"(c))
#define MUL2(d, a, b) \
    asm("mul.rn.f32x2 %0, %1, %2;" : "=l"(d) : "l"(a), "l"(b))
#define ADD2(d, a, b) \
    asm("add.rn.f32x2 %0, %1, %2;" : "=l"(d) : "l"(a), "l"(b))
#define PACK2(d, lo, hi) \
    asm("mov.b64 %0, {%1, %2};" : "=l"(d) : "f"(lo), "f"(hi))
#define UNPACK2(lo, hi, d) \
    asm("mov.b64 {%0, %1}, %2;" : "=f"(lo), "=f"(hi) : "l"(d))
#define RCP(d, s) \
    asm("rcp.approx.f32 %0, %1;" : "=f"(d) : "f"(s))

// shared tile: per pair-of-j slot, 4 ull = {x2, y2, z2, pad} (32B, keeps
// 16B alignment so (x2,y2) goes out as one LDS.128)
#define SLOTS (JT / 2)   // 64

template <bool DIAG>
__device__ __forceinline__ void lj_loop(const ull* __restrict__ sj,
                                        ull xi2, ull yi2, ull zi2,
                                        ull& a12, ull& a6) {
    const ull neg1 = 0xBF800000BF800000ULL;  // (-1.0f, -1.0f)
    #pragma unroll 8
    for (int k = 0; k < SLOTS / 2; k++) {    // 32 slots per j-half
        const ull* s = sj + 4 * k;
        ull px = s[0];
        ull py = s[1];
        ull pz = s[2];
        ull dx, dy, dz, sq, t2, i3, inv2;
        FMA2(dx, px, neg1, xi2);             // xi - px   (x2)
        FMA2(dy, py, neg1, yi2);
        FMA2(dz, pz, neg1, zi2);
        MUL2(sq, dx, dx);
        FMA2(sq, dy, dy, sq);
        FMA2(sq, dz, dz, sq);                // squared distance (x2)
        float s0, s1;
        UNPACK2(s0, s1, sq);
        if (DIAG) {
            // i == j gives sq == 0 exactly; push to huge -> rcp underflows -> 0
            s0 = (s0 == 0.f) ? 3e38f : s0;
            s1 = (s1 == 0.f) ? 3e38f : s1;
        }
        float i0, i1;
        RCP(i0, s0);
        RCP(i1, s1);
        PACK2(inv2, i0, i1);
        MUL2(t2, inv2, inv2);
        MUL2(i3, t2, inv2);                  // d^-6 (x2)
        FMA2(a12, i3, i3, a12);              // sum d^-12
        ADD2(a6, i3, a6);                    // sum d^-6
    }
}

__global__ __launch_bounds__(TPB) void lj_tri_kernel(const float* __restrict__ x,
                                                     float* __restrict__ out) {
    const int b = blockIdx.z;
    const float* xb = x + b * NPTS * 3;
    const int t = threadIdx.x;
    const int w = t >> 5, lane = t & 31;

    // ---------------- harmonic block (blockIdx.x == NTRI) ----------------
    if (blockIdx.x == NTRI) {
        float sx = 0.f, sy = 0.f, sz = 0.f, s2 = 0.f;
        for (int i = t; i < NPTS; i += TPB) {
            float px = xb[3 * i + 0];
            float py = xb[3 * i + 1];
            float pz = xb[3 * i + 2];
            sx += px; sy += py; sz += pz;
            s2 = fmaf(px, px, s2);
            s2 = fmaf(py, py, s2);
            s2 = fmaf(pz, pz, s2);
        }
        #pragma unroll
        for (int o = 16; o; o >>= 1) {
            sx += __shfl_xor_sync(0xffffffffu, sx, o);
            sy += __shfl_xor_sync(0xffffffffu, sy, o);
            sz += __shfl_xor_sync(0xffffffffu, sz, o);
            s2 += __shfl_xor_sync(0xffffffffu, s2, o);
        }
        __shared__ float red[4][TPB / 32];
        if (lane == 0) { red[0][w] = sx; red[1][w] = sy; red[2][w] = sz; red[3][w] = s2; }
        __syncthreads();
        if (t == 0) {
            float tx = 0.f, ty = 0.f, tz = 0.f, t2 = 0.f;
            #pragma unroll
            for (int k = 0; k < TPB / 32; k++) {
                tx += red[0][k]; ty += red[1][k]; tz += red[2][k]; t2 += red[3][k];
            }
            float com2 = (tx * tx + ty * ty + tz * tz) * (1.0f / NPTS);
            float harm = 0.25f * (t2 - com2);  // 0.5 * k(=0.5) * sum((x-com)^2)
            atomicAdd(out + b, -harm);
        }
        return;
    }

    // ---------------- triangle tile mapping ----------------
    const int tid = blockIdx.x;
    int by = (int)((sqrtf(8.0f * tid + 1.0f) - 1.0f) * 0.5f);
    while ((by + 1) * (by + 2) / 2 <= tid) by++;
    while (by * (by + 1) / 2 > tid) by--;
    const int bx = tid - by * (by + 1) / 2;
    const bool diag = (bx == by);

    // ---------------- stage j tile: interleaved {x2,y2,z2,pad} ----------------
    __shared__ ull sj[SLOTS * 4];
    const int j0 = bx * JT;
    if (t < JT) {
        const float* p = xb + (j0 + t) * 3;
        float* shf = (float*)sj;
        const int k = t >> 1, h = t & 1;
        shf[8 * k + 0 + h] = p[0];   // x pair
        shf[8 * k + 2 + h] = p[1];   // y pair
        shf[8 * k + 4 + h] = p[2];   // z pair
    }
    __syncthreads();

    const int i = by * IT + (t & (IT - 1));
    const int jh = t >> 7;           // which j-half this thread sweeps
    const float xi = xb[3 * i + 0];
    const float yi = xb[3 * i + 1];
    const float zi = xb[3 * i + 2];
    ull xi2, yi2, zi2;
    PACK2(xi2, xi, xi);
    PACK2(yi2, yi, yi);
    PACK2(zi2, zi, zi);

    ull a12 = 0ull, a6 = 0ull;
    const ull* sjh = sj + jh * (SLOTS / 2) * 4;

    if (diag)
        lj_loop<true>(sjh, xi2, yi2, zi2, a12, a6);
    else
        lj_loop<false>(sjh, xi2, yi2, zi2, a12, a6);

    float a12l, a12h, a6l, a6h;
    UNPACK2(a12l, a12h, a12);
    UNPACK2(a6l, a6h, a6);
    float pot = 4.0f * ((a12l + a12h) - (a6l + a6h));

    #pragma unroll
    for (int o = 16; o; o >>= 1)
        pot += __shfl_xor_sync(0xffffffffu, pot, o);

    __shared__ float wsum[TPB / 32];
    if (lane == 0) wsum[w] = pot;
    __syncthreads();

    if (t == 0) {
        float v = 0.f;
        #pragma unroll
        for (int k = 0; k < TPB / 32; k++) v += wsum[k];
        // off-diag tiles: each unordered pair once (weight 1);
        // diag tiles: full ordered tile (weight 0.5). Negate for log_prob.
        const float wgt = diag ? 0.5f : 1.0f;
        atomicAdd(out + b, -wgt * v);
    }
}

extern "C" void kernel_launch(void* const* d_in, const int* in_sizes, int n_in,
                              void* d_out, int out_size) {
    const float* x = (const float*)d_in[0];
    float* out = (float*)d_out;

    cudaMemsetAsync(out, 0, NB * sizeof(float));

    dim3 grid(NTRI + 1, 1, NB);  // 136 pair tiles + 1 harmonic block, x4 batches
    lj_tri_kernel<<<grid, TPB>>>(x, out);
}